// round 16
// baseline (speedup 1.0000x reference)
#include <cuda_runtime.h>
#include <cuda_fp16.h>
#include <cstdint>

// Problem constants (fixed by setup_inputs)
#define Bv 32
#define Lv 512
#define Dv 384
#define Kv 8192
#define Nv (Bv*Lv)            // 16384 rows

// Output layout: concatenated float32 tuple
#define OFF_Q    ((size_t)0)
#define OFF_IDX  ((size_t)Nv*Dv)
#define OFF_LOSS (OFF_IDX + (size_t)Nv)
#define OFF_NCS  (OFF_LOSS + 1)
#define OFF_NES  (OFF_NCS + (size_t)Kv)
#define OFF_NCB  (OFF_NES + (size_t)Kv*Dv)

#define NCH 24                 // k16 chunks (384/16)
#define KSPLIT 8
#define NTILES 8               // colblocks per CTA
#define NITER (NTILES * NCH)   // 192
#define CAND_MAX (4u << 20)    // 4M candidates

// phase-1 SMEM map: A resident 24*4096, B 4-stage*4096, rbest 1KB
#define SMEM_B   (NCH * 4096)                  // 98304
#define SMEM_RB  (SMEM_B + 4 * 4096)           // 114688
#define SMEM_DYN (SMEM_RB + 128 * 8)           // 115712

// Scratch (static device globals: no allocation allowed)
__device__ unsigned long long g_pack[Nv];    // phase-1 approx running min
__device__ unsigned long long g_final[Nv];   // exact min over candidates
__device__ float g_counts[Kv];
__device__ float g_embed[(size_t)Kv*Dv];
__device__ float g_c2[Kv];
__device__ float g_sumsq;
__device__ float g_sum_ema;
__device__ unsigned g_cnt;
__device__ unsigned g_z2max_u;
__device__ unsigned g_c2max_u;
__device__ unsigned g_cand[CAND_MAX];

// fp16 h0-only packet arrays in mma-fragment order.
// A: [rowblock 128][chunk 24][4096 B]; packet(b,g,q) 16B = [loww0 loww1 hiw0 hiw1]
// B: [colblock 64][chunk 24][4096 B]; per chunk: [wn 4][1KB pair slice],
//    slice layout: ((g*4+q)*4 + n2)*8 -> per-thread 32B contiguous
//    (+3 stage padding so the phase-1 producer can run unguarded)
__device__ uint4 g_zpack[(size_t)128 * NCH * 4096 / 16];
__device__ uint4 g_cpack[((size_t)64 * NCH * 4096 + 3 * 4096) / 16];

__device__ __forceinline__ uint32_t smem_u32(const void* p) {
    uint32_t a;
    asm("{ .reg .u64 t; cvta.to.shared.u64 t, %1; cvt.u32.u64 %0, t; }"
        : "=r"(a) : "l"(p));
    return a;
}

// order-preserving pack (ties -> lowest col wins, matching argmin)
__device__ __forceinline__ unsigned long long packsc(float s, unsigned col) {
    unsigned u = __float_as_uint(s);
    u ^= ((unsigned)(((int)u) >> 31)) | 0x80000000u;
    return ((unsigned long long)u << 32) | col;
}
// inverse of the score half of packsc
__device__ __forceinline__ float unpack_hi(unsigned long long v) {
    unsigned u = (unsigned)(v >> 32);
    u = (u >> 31) ? (u ^ 0x80000000u) : ~u;
    return __uint_as_float(u);
}

__device__ __forceinline__ uint32_t packh2(float a, float b) {
    __half2 h = __halves2half2(__float2half_rn(a), __float2half_rn(b));
    return *(uint32_t*)&h;
}

__device__ __forceinline__ void cand_push(int row, int col) {
    unsigned i = atomicAdd(&g_cnt, 1u);
    if (i < CAND_MAX)
        g_cand[i] = ((unsigned)row << 13) | (unsigned)col;
}

// ---------------------------------------------------------------------------
// Kernel 0: init scratch
// ---------------------------------------------------------------------------
__global__ void vq_init_kernel() {
    int i = blockIdx.x * blockDim.x + threadIdx.x;
    int stride = gridDim.x * blockDim.x;
    for (size_t j = i; j < (size_t)Kv * Dv; j += stride) g_embed[j] = 0.f;
    for (int j = i; j < Kv; j += stride) g_counts[j] = 0.f;
    for (int j = i; j < Nv; j += stride) { g_pack[j] = ~0ull; g_final[j] = ~0ull; }
    if (i == 0) {
        g_sumsq = 0.f; g_sum_ema = 0.f; g_cnt = 0u;
        g_z2max_u = 0u; g_c2max_u = 0u;
    }
}

// ---------------------------------------------------------------------------
// Kernel 1 (fused): blocks [0,Kv): codebook norms + max
//                   blocks [Kv,Kv+Nv): z row norm max
//                   block Kv+Nv: sum of ema_cluster_size
// ---------------------------------------------------------------------------
__global__ void vq_norms_kernel(const float* __restrict__ cb,
                                const float* __restrict__ z,
                                const float* __restrict__ ema_cs) {
    int b = blockIdx.x;
    int t = threadIdx.x;  // 128
    __shared__ float ws[4];
    if (b == Kv + Nv) {
        float s = 0.f;
        for (int j = t; j < Kv; j += 128) s += ema_cs[j];
#pragma unroll
        for (int o = 16; o; o >>= 1) s += __shfl_down_sync(0xffffffffu, s, o);
        if ((t & 31) == 0) ws[t >> 5] = s;
        __syncthreads();
        if (t == 0) g_sum_ema = ws[0] + ws[1] + ws[2] + ws[3];
        return;
    }
    const float* r = (b < Kv) ? (cb + (size_t)b * Dv)
                              : (z + (size_t)(b - Kv) * Dv);
    float s = 0.f;
#pragma unroll
    for (int u = 0; u < 3; ++u) { float v = r[t + u * 128]; s = fmaf(v, v, s); }
#pragma unroll
    for (int o = 16; o; o >>= 1) s += __shfl_down_sync(0xffffffffu, s, o);
    if ((t & 31) == 0) ws[t >> 5] = s;
    __syncthreads();
    if (t == 0) {
        float v = ws[0] + ws[1] + ws[2] + ws[3];
        if (b < Kv) {
            g_c2[b] = v;
            atomicMax(&g_c2max_u, __float_as_uint(v));  // v>=0: uint order == float
        } else {
            atomicMax(&g_z2max_u, __float_as_uint(v));
        }
    }
}

// ---------------------------------------------------------------------------
// Kernel 2 (fused): pre-split z AND codebook into h0 packets
// ---------------------------------------------------------------------------
__global__ void vq_split_kernel(const float* __restrict__ z,
                                const float* __restrict__ cb) {
    int i = blockIdx.x * 256 + threadIdx.x;   // exactly (Nv+Kv)*NCH threads
    if (i < Nv * NCH) {
        int ch = i % NCH;
        int r = i / NCH;
        const float* src = z + (size_t)r * Dv + ch * 16;
        float x[16];
#pragma unroll
        for (int u = 0; u < 4; ++u)
            *(float4*)&x[u * 4] = *(const float4*)(src + u * 4);
        int rb = r >> 7, rl = r & 127;
        int b = rl >> 4;
        int role = (rl >> 3) & 1;      // 0: low row of pair, 1: high row
        int g = rl & 7;
        char* dst = (char*)g_zpack + (size_t)rb * (NCH * 4096) +
                    (size_t)ch * 4096 +
                    (size_t)((b * 8 + g) * 4) * 16 + role * 8;
#pragma unroll
        for (int q = 0; q < 4; ++q) {
            uint2 h;
            h.x = packh2(x[2 * q], x[2 * q + 1]);          // w0
            h.y = packh2(x[2 * q + 8], x[2 * q + 9]);      // w1
            *(uint2*)(dst + q * 16) = h;
        }
    } else {
        int j = i - Nv * NCH;          // exactly Kv*NCH threads
        int ch = j % NCH;
        int n = j / NCH;
        const float* src = cb + (size_t)n * Dv + ch * 16;
        float x[16];
#pragma unroll
        for (int u = 0; u < 4; ++u)
            *(float4*)&x[u * 4] = *(const float4*)(src + u * 4);
        int cbk = n >> 7, nl = n & 127;
        int wn2 = nl >> 5, g2 = nl & 7, nn2 = (nl >> 3) & 3;
        // pair-sliced, thread-contiguous layout:
        //   wn*1024 + ((g*4+q)*4 + n2)*8 = wn*1024 + g*128 + q*32 + n2*8
        char* dst = (char*)g_cpack + (size_t)cbk * (NCH * 4096) +
                    (size_t)ch * 4096 + wn2 * 1024 + g2 * 128 + nn2 * 8;
#pragma unroll
        for (int q = 0; q < 4; ++q) {
            uint2 h;
            h.x = packh2(x[2 * q], x[2 * q + 1]);          // w0
            h.y = packh2(x[2 * q + 8], x[2 * q + 9]);      // w1
            *(uint2*)(dst + q * 32) = h;
        }
    }
}

// ---------------------------------------------------------------------------
// Kernel 3 (phase 1): h0*h0 mma GEMM, A resident, per-pair B staging
//   256 thr (8 warps 2x4), 2 CTAs/SM; named barriers (64-thread pairs)
//   replace the block-wide sync in the mainloop — no convoy effect.
// ---------------------------------------------------------------------------
__device__ __forceinline__ void mma_f16(float* c,
                                        uint32_t a0, uint32_t a1,
                                        uint32_t a2, uint32_t a3,
                                        uint32_t b0, uint32_t b1) {
    asm volatile(
        "mma.sync.aligned.m16n8k16.row.col.f32.f16.f16.f32 "
        "{%0,%1,%2,%3}, {%4,%5,%6,%7}, {%8,%9}, {%0,%1,%2,%3};"
        : "+f"(c[0]), "+f"(c[1]), "+f"(c[2]), "+f"(c[3])
        : "r"(a0), "r"(a1), "r"(a2), "r"(a3), "r"(b0), "r"(b1));
}

extern __shared__ char dynsm[];

__global__ void __launch_bounds__(256, 2) vq_phase1() {
    const int tid = threadIdx.x;
    const int lane = tid & 31;
    const int wid = tid >> 5;
    const int wm = wid & 1;       // warp m position (0..1)
    const int wn = wid >> 1;      // warp n position (0..3)
    const int rb = blockIdx.x;
    const int row0 = rb * 128;
    const int cb0 = blockIdx.y * NTILES;   // first colblock of this CTA

    char* smem = dynsm;
    unsigned long long* rbest = (unsigned long long*)(dynsm + SMEM_RB);
    const uint32_t sbase = smem_u32(smem);

    if (tid < 128) rbest[tid] = ~0ull;

    // threshold (uniform; from norms kernel)
    const float tadd = (1.0f / 256.0f) *
        sqrtf(__uint_as_float(g_z2max_u) * __uint_as_float(g_c2max_u)) + 1e-3f;

    const int g = lane >> 2, q = lane & 3;
    const int bar_id = 1 + wn;    // named barrier per warp pair (64 threads)

    const char* gA = (const char*)g_zpack + (size_t)rb * (NCH * 4096);
    // per-thread slot within the pair's 1KB B slice
    const uint32_t bslice = (uint32_t)(wn * 1024 + (wm * 32 + lane) * 16);
    const char* gBsrc = (const char*)g_cpack + (size_t)cb0 * (NCH * 4096)
                        + bslice;
    const uint32_t dstB = sbase + SMEM_B + bslice;   // + stage*4096

    // prologue: A (group 0) + B stages 0..2 (groups 1..3)
    {
        const char* sa = gA + tid * 16;
        uint32_t da = sbase + tid * 16;
#pragma unroll
        for (int c = 0; c < NCH; ++c)
            asm volatile("cp.async.cg.shared.global [%0], [%1], 16;"
                         :: "r"(da + c * 4096), "l"(sa + c * 4096));
        asm volatile("cp.async.commit_group;");
        asm volatile("cp.async.cg.shared.global [%0], [%1], 16;"
                     :: "r"(dstB), "l"(gBsrc));
        asm volatile("cp.async.commit_group;");
        asm volatile("cp.async.cg.shared.global [%0], [%1], 16;"
                     :: "r"(dstB + 4096), "l"(gBsrc + 4096));
        asm volatile("cp.async.commit_group;");
        asm volatile("cp.async.cg.shared.global [%0], [%1], 16;"
                     :: "r"(dstB + 8192), "l"(gBsrc + 8192));
        asm volatile("cp.async.commit_group;");
        gBsrc += 3 * 4096;
        asm volatile("cp.async.wait_group 3;");   // A retired
        __syncthreads();                          // A visible to all
    }

    // per-thread constant SMEM offsets
    const uint32_t aoff = (uint32_t)(((4 * wm) * 8 + g) * 64 + q * 16);
    const uint32_t boff = (uint32_t)(wn * 1024 + lane * 32);

    float acc[4][4][4];

#pragma unroll 1
    for (int nt = 0; nt < NTILES; ++nt) {
#pragma unroll
        for (int mt = 0; mt < 4; ++mt)
#pragma unroll
            for (int n2 = 0; n2 < 4; ++n2)
#pragma unroll
                for (int w = 0; w < 4; ++w) acc[mt][n2][w] = 0.f;

        const char* pAc = smem;
#pragma unroll 1
        for (int cb4 = 0; cb4 < NCH / 4; ++cb4) {
#pragma unroll
            for (int u = 0; u < 4; ++u) {
                asm volatile("cp.async.wait_group 2;");
                asm volatile("bar.sync %0, 64;" :: "r"(bar_id));

                // A fragments from resident chunk
                uint32_t ah[4][4];
                const char* pa = pAc + aoff;
#pragma unroll
                for (int mt = 0; mt < 4; ++mt) {
                    uint4 p = *(const uint4*)(pa + mt * 512);
                    ah[mt][0] = p.x; ah[mt][2] = p.y;
                    ah[mt][1] = p.z; ah[mt][3] = p.w;
                }
                // B fragments: 2 x LDS.128 (thread-contiguous 32B)
                const char* pb = smem + SMEM_B + u * 4096 + boff;
                uint4 p0 = *(const uint4*)pb;
                uint4 p1 = *(const uint4*)(pb + 16);
                uint32_t bh[4][2];
                bh[0][0] = p0.x; bh[0][1] = p0.y;
                bh[1][0] = p0.z; bh[1][1] = p0.w;
                bh[2][0] = p1.x; bh[2][1] = p1.y;
                bh[3][0] = p1.z; bh[3][1] = p1.w;

#pragma unroll
                for (int mt = 0; mt < 4; ++mt)
#pragma unroll
                    for (int n2 = 0; n2 < 4; ++n2)
                        mma_f16(acc[mt][n2], ah[mt][0], ah[mt][1],
                                ah[mt][2], ah[mt][3], bh[n2][0], bh[n2][1]);

                // producer: unconditional (g_cpack padded), linear pointer
                asm volatile("cp.async.cg.shared.global [%0], [%1], 16;"
                             :: "r"(dstB + (((u + 3) & 3) * 4096)),
                                "l"(gBsrc));
                gBsrc += 4096;
                asm volatile("cp.async.commit_group;");
                pAc += 4096;
            }
        }

        // ---- per-n-tile epilogue ----
        const int nbase = (cb0 + nt) * 128;
        // 1) tile min -> rbest (running across tiles)
#pragma unroll
        for (int mt = 0; mt < 4; ++mt) {
            int r0l = g + mt * 16 + wm * 64;
            unsigned long long bst0 = ~0ull, bst1 = ~0ull;
#pragma unroll
            for (int n2 = 0; n2 < 4; ++n2) {
                unsigned gcol = (unsigned)(nbase + n2 * 8 + wn * 32 + 2 * q);
                float c2a = __ldg(&g_c2[gcol]);
                float c2b = __ldg(&g_c2[gcol + 1]);
                unsigned long long p;
                p = packsc(fmaf(-2.f, acc[mt][n2][0], c2a), gcol);
                if (p < bst0) bst0 = p;
                p = packsc(fmaf(-2.f, acc[mt][n2][1], c2b), gcol + 1);
                if (p < bst0) bst0 = p;
                p = packsc(fmaf(-2.f, acc[mt][n2][2], c2a), gcol);
                if (p < bst1) bst1 = p;
                p = packsc(fmaf(-2.f, acc[mt][n2][3], c2b), gcol + 1);
                if (p < bst1) bst1 = p;
            }
#pragma unroll
            for (int off = 1; off <= 2; off <<= 1) {
                unsigned long long o0 = __shfl_xor_sync(0xffffffffu, bst0, off);
                unsigned long long o1 = __shfl_xor_sync(0xffffffffu, bst1, off);
                if (o0 < bst0) bst0 = o0;
                if (o1 < bst1) bst1 = o1;
            }
            if (q == 0) {
                atomicMin(&rbest[r0l], bst0);
                atomicMin(&rbest[r0l + 8], bst1);
            }
        }
        __syncthreads();
        // 2) merge with global running min
        if (tid < 128) {
            unsigned long long loc = rbest[tid];
            unsigned long long old = atomicMin(&g_pack[row0 + tid], loc);
            if (old < loc) rbest[tid] = old;
        }
        __syncthreads();
        // 3) candidate collection: score < running_min + tadd
#pragma unroll
        for (int mt = 0; mt < 4; ++mt) {
            int r0l = g + mt * 16 + wm * 64;
            float thr0 = unpack_hi(rbest[r0l]) + tadd;
            float thr1 = unpack_hi(rbest[r0l + 8]) + tadd;
#pragma unroll
            for (int n2 = 0; n2 < 4; ++n2) {
                unsigned gcol = (unsigned)(nbase + n2 * 8 + wn * 32 + 2 * q);
                float c2a = __ldg(&g_c2[gcol]);
                float c2b = __ldg(&g_c2[gcol + 1]);
                float s;
                s = fmaf(-2.f, acc[mt][n2][0], c2a);
                if (s < thr0) cand_push(row0 + r0l, gcol);
                s = fmaf(-2.f, acc[mt][n2][1], c2b);
                if (s < thr0) cand_push(row0 + r0l, gcol + 1);
                s = fmaf(-2.f, acc[mt][n2][2], c2a);
                if (s < thr1) cand_push(row0 + r0l + 8, gcol);
                s = fmaf(-2.f, acc[mt][n2][3], c2b);
                if (s < thr1) cand_push(row0 + r0l + 8, gcol + 1);
            }
        }
        __syncthreads();   // rbest stable before next n-tile epilogue
    }
}

// ---------------------------------------------------------------------------
// Kernel 3b (phase 2): exact fp32 rescore of candidates
// ---------------------------------------------------------------------------
__global__ void vq_rescore(const float* __restrict__ z,
                           const float* __restrict__ cb) {
    const int lane = threadIdx.x & 31;
    const unsigned gw = (blockIdx.x * blockDim.x + threadIdx.x) >> 5;
    const unsigned nw = (gridDim.x * blockDim.x) >> 5;
    unsigned cnt = g_cnt;
    if (cnt > CAND_MAX) cnt = CAND_MAX;
    for (unsigned i = gw; i < cnt; i += nw) {
        unsigned e = g_cand[i];
        int row = (int)(e >> 13);
        int col = (int)(e & 8191u);
        const float* zr = z + (size_t)row * Dv;
        const float* cr = cb + (size_t)col * Dv;
        float s = 0.f;
#pragma unroll
        for (int j = 0; j < 12; ++j) {
            int d = lane + j * 32;
            s = fmaf(__ldg(&zr[d]), __ldg(&cr[d]), s);
        }
#pragma unroll
        for (int o = 16; o; o >>= 1) s += __shfl_down_sync(0xffffffffu, s, o);
        if (lane == 0) {
            float sc = fmaf(-2.f, s, __ldg(&g_c2[col]));
            atomicMin(&g_final[row], packsc(sc, (unsigned)col));
        }
    }
}

// ---------------------------------------------------------------------------
// Kernel 4: gather quantized, straight-through, loss partial, EMA scatter
// ---------------------------------------------------------------------------
__global__ void vq_gather_kernel(const float* __restrict__ z,
                                 const float* __restrict__ cb,
                                 float* __restrict__ out,
                                 long long out_size) {
    int n = blockIdx.x;
    int t = threadIdx.x;  // 128
    int idx = (int)(g_final[n] & 0xffffffffull);
    const float* zr = z + (size_t)n * Dv;
    const float* cr = cb + (size_t)idx * Dv;
    float ss = 0.f;
#pragma unroll
    for (int u = 0; u < 3; ++u) {
        int d = t + u * 128;
        float zv = zr[d];
        float q = cr[d];
        out[OFF_Q + (size_t)n * Dv + d] = zv + (q - zv);
        float df = zv - q;
        ss = fmaf(df, df, ss);
        atomicAdd(&g_embed[(size_t)idx * Dv + d], zv);
    }
#pragma unroll
    for (int o = 16; o; o >>= 1) ss += __shfl_down_sync(0xffffffffu, ss, o);
    __shared__ float ws[4];
    if ((t & 31) == 0) ws[t >> 5] = ss;
    __syncthreads();
    if (t == 0) {
        atomicAdd(&g_sumsq, ws[0] + ws[1] + ws[2] + ws[3]);
        atomicAdd(&g_counts[idx], 1.0f);
        if (out_size > (long long)OFF_IDX) out[OFF_IDX + n] = (float)idx;
    }
}

// ---------------------------------------------------------------------------
// Kernel 5: finalize EMA outputs + loss
// ---------------------------------------------------------------------------
__global__ void vq_finalize_kernel(const float* __restrict__ ema_cs,
                                   const float* __restrict__ ema_es,
                                   float* __restrict__ out,
                                   long long out_size) {
    int k = blockIdx.x;
    int t = threadIdx.x;  // 128
    float nn = 0.99f * g_sum_ema + 0.01f * (float)Nv;
    float ncs = 0.99f * ema_cs[k] + 0.01f * g_counts[k];
    float smoothed = (ncs + 1e-5f) / (nn + (float)Kv * 1e-5f) * nn;
    if (t == 0 && out_size > (long long)OFF_NCS) out[OFF_NCS + k] = ncs;
    if (t == 0 && k == 0 && out_size > (long long)OFF_LOSS)
        out[OFF_LOSS] = 1.25f * g_sumsq / (float)((size_t)Nv * Dv);
    if (out_size > (long long)OFF_NES) {
#pragma unroll
        for (int u = 0; u < 3; ++u) {
            int d = t + u * 128;
            size_t o = (size_t)k * Dv + d;
            float nes = 0.99f * ema_es[o] + 0.01f * g_embed[o];
            out[OFF_NES + o] = nes;
            out[OFF_NCB + o] = nes / smoothed;
        }
    }
}

// ---------------------------------------------------------------------------
extern "C" void kernel_launch(void* const* d_in, const int* in_sizes, int n_in,
                              void* d_out, int out_size) {
    const float* z       = (const float*)d_in[0];
    const float* cb      = (const float*)d_in[1];
    const float* ema_cs  = (const float*)d_in[2];
    const float* ema_es  = (const float*)d_in[3];
    float* out = (float*)d_out;
    (void)in_sizes; (void)n_in;

    static int attr_done = 0;
    if (!attr_done) {
        cudaFuncSetAttribute(vq_phase1,
                             cudaFuncAttributeMaxDynamicSharedMemorySize,
                             SMEM_DYN);
        attr_done = 1;
    }

    vq_init_kernel<<<2048, 256>>>();
    vq_norms_kernel<<<Kv + Nv + 1, 128>>>(cb, z, ema_cs);
    vq_split_kernel<<<((Nv + Kv) * NCH) / 256, 256>>>(z, cb);
    vq_phase1<<<dim3(Nv / 128, KSPLIT), 256, SMEM_DYN>>>();   // launch index 3 -> profiled
    vq_rescore<<<512, 256>>>(z, cb);
    vq_gather_kernel<<<Nv, 128>>>(z, cb, out, (long long)out_size);
    vq_finalize_kernel<<<Kv, 128>>>(ema_cs, ema_es, out, (long long)out_size);
}

// round 17
// speedup vs baseline: 1.0737x; 1.0737x over previous
#include <cuda_runtime.h>
#include <cuda_fp16.h>
#include <cstdint>

// Problem constants (fixed by setup_inputs)
#define Bv 32
#define Lv 512
#define Dv 384
#define Kv 8192
#define Nv (Bv*Lv)            // 16384 rows

// Output layout: concatenated float32 tuple
#define OFF_Q    ((size_t)0)
#define OFF_IDX  ((size_t)Nv*Dv)
#define OFF_LOSS (OFF_IDX + (size_t)Nv)
#define OFF_NCS  (OFF_LOSS + 1)
#define OFF_NES  (OFF_NCS + (size_t)Kv)
#define OFF_NCB  (OFF_NES + (size_t)Kv*Dv)

#define NCH 24                 // k16 chunks (384/16)
#define KSPLIT 8
#define NTILES 8               // colblocks per CTA
#define NITER (NTILES * NCH)   // 192
#define CAND_MAX (4u << 20)    // 4M candidates

// phase-1 SMEM map: A resident 24*4096, B 2-stage*8192 (per-thread slots), rbest
#define SMEM_B   (NCH * 4096)                  // 98304
#define SMEM_RB  (SMEM_B + 2 * 8192)           // 114688
#define SMEM_DYN (SMEM_RB + 128 * 8)           // 115712 -> fits 2 CTAs/SM

// Scratch (static device globals: no allocation allowed)
__device__ unsigned long long g_pack[Nv];    // phase-1 approx running min
__device__ unsigned long long g_final[Nv];   // exact min over candidates
__device__ float g_counts[Kv];
__device__ float g_embed[(size_t)Kv*Dv];
__device__ float g_c2[Kv];
__device__ float g_sumsq;
__device__ float g_sum_ema;
__device__ unsigned g_cnt;
__device__ unsigned g_z2max_u;
__device__ unsigned g_c2max_u;
__device__ unsigned g_cand[CAND_MAX];

// fp16 h0-only packet arrays in mma-fragment order.
// A: [rowblock 128][chunk 24][4096 B]; packet(b,g,q) 16B = [loww0 loww1 hiw0 hiw1]
// B: [colblock 64][chunk 24][4096 B]; per chunk: [wn 4][slot l=g*4+q 32][n2 8B x4]
//    (+3 chunk padding so the phase-1 producer can run unguarded)
__device__ uint4 g_zpack[(size_t)128 * NCH * 4096 / 16];
__device__ uint4 g_cpack[((size_t)64 * NCH * 4096 + 3 * 4096) / 16];

__device__ __forceinline__ uint32_t smem_u32(const void* p) {
    uint32_t a;
    asm("{ .reg .u64 t; cvta.to.shared.u64 t, %1; cvt.u32.u64 %0, t; }"
        : "=r"(a) : "l"(p));
    return a;
}

// order-preserving pack (ties -> lowest col wins, matching argmin)
__device__ __forceinline__ unsigned long long packsc(float s, unsigned col) {
    unsigned u = __float_as_uint(s);
    u ^= ((unsigned)(((int)u) >> 31)) | 0x80000000u;
    return ((unsigned long long)u << 32) | col;
}
// inverse of the score half of packsc
__device__ __forceinline__ float unpack_hi(unsigned long long v) {
    unsigned u = (unsigned)(v >> 32);
    u = (u >> 31) ? (u ^ 0x80000000u) : ~u;
    return __uint_as_float(u);
}

__device__ __forceinline__ uint32_t packh2(float a, float b) {
    __half2 h = __halves2half2(__float2half_rn(a), __float2half_rn(b));
    return *(uint32_t*)&h;
}

__device__ __forceinline__ void cand_push(int row, int col) {
    unsigned i = atomicAdd(&g_cnt, 1u);
    if (i < CAND_MAX)
        g_cand[i] = ((unsigned)row << 13) | (unsigned)col;
}

// ---------------------------------------------------------------------------
// Kernel 0: init scratch
// ---------------------------------------------------------------------------
__global__ void vq_init_kernel() {
    int i = blockIdx.x * blockDim.x + threadIdx.x;
    int stride = gridDim.x * blockDim.x;
    for (size_t j = i; j < (size_t)Kv * Dv; j += stride) g_embed[j] = 0.f;
    for (int j = i; j < Kv; j += stride) g_counts[j] = 0.f;
    for (int j = i; j < Nv; j += stride) { g_pack[j] = ~0ull; g_final[j] = ~0ull; }
    if (i == 0) {
        g_sumsq = 0.f; g_sum_ema = 0.f; g_cnt = 0u;
        g_z2max_u = 0u; g_c2max_u = 0u;
    }
}

// ---------------------------------------------------------------------------
// Kernel 1 (fused): blocks [0,Kv): codebook norms + max
//                   blocks [Kv,Kv+Nv): z row norm max
//                   block Kv+Nv: sum of ema_cluster_size
// ---------------------------------------------------------------------------
__global__ void vq_norms_kernel(const float* __restrict__ cb,
                                const float* __restrict__ z,
                                const float* __restrict__ ema_cs) {
    int b = blockIdx.x;
    int t = threadIdx.x;  // 128
    __shared__ float ws[4];
    if (b == Kv + Nv) {
        float s = 0.f;
        for (int j = t; j < Kv; j += 128) s += ema_cs[j];
#pragma unroll
        for (int o = 16; o; o >>= 1) s += __shfl_down_sync(0xffffffffu, s, o);
        if ((t & 31) == 0) ws[t >> 5] = s;
        __syncthreads();
        if (t == 0) g_sum_ema = ws[0] + ws[1] + ws[2] + ws[3];
        return;
    }
    const float* r = (b < Kv) ? (cb + (size_t)b * Dv)
                              : (z + (size_t)(b - Kv) * Dv);
    float s = 0.f;
#pragma unroll
    for (int u = 0; u < 3; ++u) { float v = r[t + u * 128]; s = fmaf(v, v, s); }
#pragma unroll
    for (int o = 16; o; o >>= 1) s += __shfl_down_sync(0xffffffffu, s, o);
    if ((t & 31) == 0) ws[t >> 5] = s;
    __syncthreads();
    if (t == 0) {
        float v = ws[0] + ws[1] + ws[2] + ws[3];
        if (b < Kv) {
            g_c2[b] = v;
            atomicMax(&g_c2max_u, __float_as_uint(v));  // v>=0: uint order == float
        } else {
            atomicMax(&g_z2max_u, __float_as_uint(v));
        }
    }
}

// ---------------------------------------------------------------------------
// Kernel 2 (fused): pre-split z AND codebook into h0 packets
// ---------------------------------------------------------------------------
__global__ void vq_split_kernel(const float* __restrict__ z,
                                const float* __restrict__ cb) {
    int i = blockIdx.x * 256 + threadIdx.x;   // exactly (Nv+Kv)*NCH threads
    if (i < Nv * NCH) {
        int ch = i % NCH;
        int r = i / NCH;
        const float* src = z + (size_t)r * Dv + ch * 16;
        float x[16];
#pragma unroll
        for (int u = 0; u < 4; ++u)
            *(float4*)&x[u * 4] = *(const float4*)(src + u * 4);
        int rb = r >> 7, rl = r & 127;
        int b = rl >> 4;
        int role = (rl >> 3) & 1;      // 0: low row of pair, 1: high row
        int g = rl & 7;
        char* dst = (char*)g_zpack + (size_t)rb * (NCH * 4096) +
                    (size_t)ch * 4096 +
                    (size_t)((b * 8 + g) * 4) * 16 + role * 8;
#pragma unroll
        for (int q = 0; q < 4; ++q) {
            uint2 h;
            h.x = packh2(x[2 * q], x[2 * q + 1]);          // w0
            h.y = packh2(x[2 * q + 8], x[2 * q + 9]);      // w1
            *(uint2*)(dst + q * 16) = h;
        }
    } else {
        int j = i - Nv * NCH;          // exactly Kv*NCH threads
        int ch = j % NCH;
        int n = j / NCH;
        const float* src = cb + (size_t)n * Dv + ch * 16;
        float x[16];
#pragma unroll
        for (int u = 0; u < 4; ++u)
            *(float4*)&x[u * 4] = *(const float4*)(src + u * 4);
        int cbk = n >> 7, nl = n & 127;
        int wn2 = nl >> 5, g2 = nl & 7, nn2 = (nl >> 3) & 3;
        // thread-slot-contiguous layout: wn*1024 + (g*4+q)*32 + n2*8
        char* dst = (char*)g_cpack + (size_t)cbk * (NCH * 4096) +
                    (size_t)ch * 4096 + wn2 * 1024 + g2 * 128 + nn2 * 8;
#pragma unroll
        for (int q = 0; q < 4; ++q) {
            uint2 h;
            h.x = packh2(x[2 * q], x[2 * q + 1]);          // w0
            h.y = packh2(x[2 * q + 8], x[2 * q + 9]);      // w1
            *(uint2*)(dst + q * 32) = h;
        }
    }
}

// ---------------------------------------------------------------------------
// Kernel 3 (phase 1): h0*h0 mma GEMM, A resident, SELF-STAGED B
//   Each thread cp.asyncs its own 32B B slice into a private SMEM slot ->
//   no barrier in the mainloop at all; warps fully decoupled.
//   2 stages x 8KB, prefetch distance 1; block syncs only in epilogue.
// ---------------------------------------------------------------------------
__device__ __forceinline__ void mma_f16(float* c,
                                        uint32_t a0, uint32_t a1,
                                        uint32_t a2, uint32_t a3,
                                        uint32_t b0, uint32_t b1) {
    asm volatile(
        "mma.sync.aligned.m16n8k16.row.col.f32.f16.f16.f32 "
        "{%0,%1,%2,%3}, {%4,%5,%6,%7}, {%8,%9}, {%0,%1,%2,%3};"
        : "+f"(c[0]), "+f"(c[1]), "+f"(c[2]), "+f"(c[3])
        : "r"(a0), "r"(a1), "r"(a2), "r"(a3), "r"(b0), "r"(b1));
}

extern __shared__ char dynsm[];

__global__ void __launch_bounds__(256, 2) vq_phase1() {
    const int tid = threadIdx.x;
    const int lane = tid & 31;
    const int wid = tid >> 5;
    const int wm = wid & 1;       // warp m position (0..1)
    const int wn = wid >> 1;      // warp n position (0..3)
    const int rb = blockIdx.x;
    const int row0 = rb * 128;
    const int cb0 = blockIdx.y * NTILES;   // first colblock of this CTA

    char* smem = dynsm;
    unsigned long long* rbest = (unsigned long long*)(dynsm + SMEM_RB);
    const uint32_t sbase = smem_u32(smem);

    if (tid < 128) rbest[tid] = ~0ull;

    // threshold (uniform; from norms kernel)
    const float tadd = (1.0f / 256.0f) *
        sqrtf(__uint_as_float(g_z2max_u) * __uint_as_float(g_c2max_u)) + 1e-3f;

    const int g = lane >> 2, q = lane & 3;

    const char* gA = (const char*)g_zpack + (size_t)rb * (NCH * 4096);
    // this thread's 32B B slice source (linear in chunk index; colblocks contiguous)
    const char* gBsrc = (const char*)g_cpack + (size_t)cb0 * (NCH * 4096)
                        + wn * 1024 + lane * 32;
    // XOR swizzle: conflict-free LDS.128 at stride-32 slots
    const uint32_t sw = (uint32_t)((lane & 4) << 2);   // 0 or 16
    const uint32_t slot0 = ((uint32_t)(tid * 32)) ^ sw;
    const uint32_t slot1 = ((uint32_t)(tid * 32 + 16)) ^ sw;
    const uint32_t dstB = sbase + SMEM_B;              // + stage*8192 + slot

    // prologue group: all 24 resident A chunks + B chunk 0 into stage 0
    {
        const char* sa = gA + tid * 16;
        uint32_t da = sbase + tid * 16;
#pragma unroll
        for (int c = 0; c < NCH; ++c)
            asm volatile("cp.async.cg.shared.global [%0], [%1], 16;"
                         :: "r"(da + c * 4096), "l"(sa + c * 4096));
        asm volatile("cp.async.cg.shared.global [%0], [%1], 16;"
                     :: "r"(dstB + slot0), "l"(gBsrc));
        asm volatile("cp.async.cg.shared.global [%0], [%1], 16;"
                     :: "r"(dstB + slot1), "l"(gBsrc + 16));
        asm volatile("cp.async.commit_group;");
        gBsrc += 4096;
        asm volatile("cp.async.wait_group 0;");
        __syncthreads();   // A visible to all threads
    }

    // per-thread constant SMEM offsets
    const uint32_t aoff = (uint32_t)(((4 * wm) * 8 + g) * 64 + q * 16);

    float acc[4][4][4];

#pragma unroll 1
    for (int nt = 0; nt < NTILES; ++nt) {
#pragma unroll
        for (int mt = 0; mt < 4; ++mt)
#pragma unroll
            for (int n2 = 0; n2 < 4; ++n2)
#pragma unroll
                for (int w = 0; w < 4; ++w) acc[mt][n2][w] = 0.f;

        const char* pAc = smem;
#pragma unroll 1
        for (int cb2 = 0; cb2 < NCH / 2; ++cb2) {
#pragma unroll
            for (int u = 0; u < 2; ++u) {
                // issue next chunk into the other stage (own slice only)
                const uint32_t ns = dstB + ((u ^ 1) * 8192);
                asm volatile("cp.async.cg.shared.global [%0], [%1], 16;"
                             :: "r"(ns + slot0), "l"(gBsrc));
                asm volatile("cp.async.cg.shared.global [%0], [%1], 16;"
                             :: "r"(ns + slot1), "l"(gBsrc + 16));
                asm volatile("cp.async.commit_group;");
                gBsrc += 4096;
                // wait for current chunk's group (own copies) — no barrier
                asm volatile("cp.async.wait_group 1;");

                // A fragments from resident chunk
                uint32_t ah[4][4];
                const char* pa = pAc + aoff;
#pragma unroll
                for (int mt = 0; mt < 4; ++mt) {
                    uint4 p = *(const uint4*)(pa + mt * 512);
                    ah[mt][0] = p.x; ah[mt][2] = p.y;
                    ah[mt][1] = p.z; ah[mt][3] = p.w;
                }
                // B fragments from own slot (stage u): 2 x LDS.128
                const char* pb = smem + SMEM_B + u * 8192;
                uint4 p0 = *(const uint4*)(pb + slot0);   // n2 = 0,1
                uint4 p1 = *(const uint4*)(pb + slot1);   // n2 = 2,3
                uint32_t bh[4][2];
                bh[0][0] = p0.x; bh[0][1] = p0.y;
                bh[1][0] = p0.z; bh[1][1] = p0.w;
                bh[2][0] = p1.x; bh[2][1] = p1.y;
                bh[3][0] = p1.z; bh[3][1] = p1.w;

#pragma unroll
                for (int mt = 0; mt < 4; ++mt)
#pragma unroll
                    for (int n2 = 0; n2 < 4; ++n2)
                        mma_f16(acc[mt][n2], ah[mt][0], ah[mt][1],
                                ah[mt][2], ah[mt][3], bh[n2][0], bh[n2][1]);

                pAc += 4096;
            }
        }

        // ---- per-n-tile epilogue ----
        const int nbase = (cb0 + nt) * 128;
        // 1) tile min -> rbest (running across tiles)
#pragma unroll
        for (int mt = 0; mt < 4; ++mt) {
            int r0l = g + mt * 16 + wm * 64;
            unsigned long long bst0 = ~0ull, bst1 = ~0ull;
#pragma unroll
            for (int n2 = 0; n2 < 4; ++n2) {
                unsigned gcol = (unsigned)(nbase + n2 * 8 + wn * 32 + 2 * q);
                float c2a = __ldg(&g_c2[gcol]);
                float c2b = __ldg(&g_c2[gcol + 1]);
                unsigned long long p;
                p = packsc(fmaf(-2.f, acc[mt][n2][0], c2a), gcol);
                if (p < bst0) bst0 = p;
                p = packsc(fmaf(-2.f, acc[mt][n2][1], c2b), gcol + 1);
                if (p < bst0) bst0 = p;
                p = packsc(fmaf(-2.f, acc[mt][n2][2], c2a), gcol);
                if (p < bst1) bst1 = p;
                p = packsc(fmaf(-2.f, acc[mt][n2][3], c2b), gcol + 1);
                if (p < bst1) bst1 = p;
            }
#pragma unroll
            for (int off = 1; off <= 2; off <<= 1) {
                unsigned long long o0 = __shfl_xor_sync(0xffffffffu, bst0, off);
                unsigned long long o1 = __shfl_xor_sync(0xffffffffu, bst1, off);
                if (o0 < bst0) bst0 = o0;
                if (o1 < bst1) bst1 = o1;
            }
            if (q == 0) {
                atomicMin(&rbest[r0l], bst0);
                atomicMin(&rbest[r0l + 8], bst1);
            }
        }
        __syncthreads();
        // 2) merge with global running min
        if (tid < 128) {
            unsigned long long loc = rbest[tid];
            unsigned long long old = atomicMin(&g_pack[row0 + tid], loc);
            if (old < loc) rbest[tid] = old;
        }
        __syncthreads();
        // 3) candidate collection: score < running_min + tadd
#pragma unroll
        for (int mt = 0; mt < 4; ++mt) {
            int r0l = g + mt * 16 + wm * 64;
            float thr0 = unpack_hi(rbest[r0l]) + tadd;
            float thr1 = unpack_hi(rbest[r0l + 8]) + tadd;
#pragma unroll
            for (int n2 = 0; n2 < 4; ++n2) {
                unsigned gcol = (unsigned)(nbase + n2 * 8 + wn * 32 + 2 * q);
                float c2a = __ldg(&g_c2[gcol]);
                float c2b = __ldg(&g_c2[gcol + 1]);
                float s;
                s = fmaf(-2.f, acc[mt][n2][0], c2a);
                if (s < thr0) cand_push(row0 + r0l, gcol);
                s = fmaf(-2.f, acc[mt][n2][1], c2b);
                if (s < thr0) cand_push(row0 + r0l, gcol + 1);
                s = fmaf(-2.f, acc[mt][n2][2], c2a);
                if (s < thr1) cand_push(row0 + r0l + 8, gcol);
                s = fmaf(-2.f, acc[mt][n2][3], c2b);
                if (s < thr1) cand_push(row0 + r0l + 8, gcol + 1);
            }
        }
        __syncthreads();   // rbest stable before next n-tile epilogue
    }
}

// ---------------------------------------------------------------------------
// Kernel 3b (phase 2): exact fp32 rescore of candidates
// ---------------------------------------------------------------------------
__global__ void vq_rescore(const float* __restrict__ z,
                           const float* __restrict__ cb) {
    const int lane = threadIdx.x & 31;
    const unsigned gw = (blockIdx.x * blockDim.x + threadIdx.x) >> 5;
    const unsigned nw = (gridDim.x * blockDim.x) >> 5;
    unsigned cnt = g_cnt;
    if (cnt > CAND_MAX) cnt = CAND_MAX;
    for (unsigned i = gw; i < cnt; i += nw) {
        unsigned e = g_cand[i];
        int row = (int)(e >> 13);
        int col = (int)(e & 8191u);
        const float* zr = z + (size_t)row * Dv;
        const float* cr = cb + (size_t)col * Dv;
        float s = 0.f;
#pragma unroll
        for (int j = 0; j < 12; ++j) {
            int d = lane + j * 32;
            s = fmaf(__ldg(&zr[d]), __ldg(&cr[d]), s);
        }
#pragma unroll
        for (int o = 16; o; o >>= 1) s += __shfl_down_sync(0xffffffffu, s, o);
        if (lane == 0) {
            float sc = fmaf(-2.f, s, __ldg(&g_c2[col]));
            atomicMin(&g_final[row], packsc(sc, (unsigned)col));
        }
    }
}

// ---------------------------------------------------------------------------
// Kernel 4: gather quantized, straight-through, loss partial, EMA scatter
// ---------------------------------------------------------------------------
__global__ void vq_gather_kernel(const float* __restrict__ z,
                                 const float* __restrict__ cb,
                                 float* __restrict__ out,
                                 long long out_size) {
    int n = blockIdx.x;
    int t = threadIdx.x;  // 128
    int idx = (int)(g_final[n] & 0xffffffffull);
    const float* zr = z + (size_t)n * Dv;
    const float* cr = cb + (size_t)idx * Dv;
    float ss = 0.f;
#pragma unroll
    for (int u = 0; u < 3; ++u) {
        int d = t + u * 128;
        float zv = zr[d];
        float q = cr[d];
        out[OFF_Q + (size_t)n * Dv + d] = zv + (q - zv);
        float df = zv - q;
        ss = fmaf(df, df, ss);
        atomicAdd(&g_embed[(size_t)idx * Dv + d], zv);
    }
#pragma unroll
    for (int o = 16; o; o >>= 1) ss += __shfl_down_sync(0xffffffffu, ss, o);
    __shared__ float ws[4];
    if ((t & 31) == 0) ws[t >> 5] = ss;
    __syncthreads();
    if (t == 0) {
        atomicAdd(&g_sumsq, ws[0] + ws[1] + ws[2] + ws[3]);
        atomicAdd(&g_counts[idx], 1.0f);
        if (out_size > (long long)OFF_IDX) out[OFF_IDX + n] = (float)idx;
    }
}

// ---------------------------------------------------------------------------
// Kernel 5: finalize EMA outputs + loss
// ---------------------------------------------------------------------------
__global__ void vq_finalize_kernel(const float* __restrict__ ema_cs,
                                   const float* __restrict__ ema_es,
                                   float* __restrict__ out,
                                   long long out_size) {
    int k = blockIdx.x;
    int t = threadIdx.x;  // 128
    float nn = 0.99f * g_sum_ema + 0.01f * (float)Nv;
    float ncs = 0.99f * ema_cs[k] + 0.01f * g_counts[k];
    float smoothed = (ncs + 1e-5f) / (nn + (float)Kv * 1e-5f) * nn;
    if (t == 0 && out_size > (long long)OFF_NCS) out[OFF_NCS + k] = ncs;
    if (t == 0 && k == 0 && out_size > (long long)OFF_LOSS)
        out[OFF_LOSS] = 1.25f * g_sumsq / (float)((size_t)Nv * Dv);
    if (out_size > (long long)OFF_NES) {
#pragma unroll
        for (int u = 0; u < 3; ++u) {
            int d = t + u * 128;
            size_t o = (size_t)k * Dv + d;
            float nes = 0.99f * ema_es[o] + 0.01f * g_embed[o];
            out[OFF_NES + o] = nes;
            out[OFF_NCB + o] = nes / smoothed;
        }
    }
}

// ---------------------------------------------------------------------------
extern "C" void kernel_launch(void* const* d_in, const int* in_sizes, int n_in,
                              void* d_out, int out_size) {
    const float* z       = (const float*)d_in[0];
    const float* cb      = (const float*)d_in[1];
    const float* ema_cs  = (const float*)d_in[2];
    const float* ema_es  = (const float*)d_in[3];
    float* out = (float*)d_out;
    (void)in_sizes; (void)n_in;

    static int attr_done = 0;
    if (!attr_done) {
        cudaFuncSetAttribute(vq_phase1,
                             cudaFuncAttributeMaxDynamicSharedMemorySize,
                             SMEM_DYN);
        attr_done = 1;
    }

    vq_init_kernel<<<2048, 256>>>();
    vq_norms_kernel<<<Kv + Nv + 1, 128>>>(cb, z, ema_cs);
    vq_split_kernel<<<((Nv + Kv) * NCH) / 256, 256>>>(z, cb);
    vq_phase1<<<dim3(Nv / 128, KSPLIT), 256, SMEM_DYN>>>();   // launch index 3 -> profiled
    vq_rescore<<<512, 256>>>(z, cb);
    vq_gather_kernel<<<Nv, 128>>>(z, cb, out, (long long)out_size);
    vq_finalize_kernel<<<Kv, 128>>>(ema_cs, ema_es, out, (long long)out_size);
}